// round 13
// baseline (speedup 1.0000x reference)
#include <cuda_runtime.h>
#include <math.h>
#include <float.h>

#define Bn 32
#define Cn 512
#define CR 64
#define Hd 64
#define Wd 64
#define HW 4096
#define EPS 1e-12f

// ---- scratch (no allocation allowed) ----
__device__ float g_avg[Bn * Cn];
__device__ float g_mx [Bn * Cn];
__device__ float g_s  [Bn * Cn];
__device__ float g_sv [4];
__device__ float g_ca [Bn * HW];
__device__ float g_cm [Bn * HW];
__device__ float g_sig[Bn * HW];

// epoch-safe monotonic counters (graph replays keep incrementing)
__device__ unsigned c_stats[Bn];      // arrivals: 32 stats blocks + 1 sv block per epoch
__device__ unsigned t_mlp  [Bn];      // waiter tickets (one mlp block per batch per epoch)
__device__ unsigned c_pool [Bn];      // arrivals: 32 pool blocks per epoch
__device__ unsigned t_conv [Bn * 8];  // waiter tickets (8 conv blocks per batch per epoch)

// ============================================================
// K1: grid = 1 + 1024 + 32 blocks, 512 threads.
//  block 0        : spectral norms sv1/sv2/sv3
//  blocks 1..1024 : per-(b,c) stats, one warp per row
//  blocks 1025+   : channel-MLP for batch b (waits on c_stats[b])
// ============================================================
__global__ void __launch_bounds__(512)
k_stats(const float* __restrict__ x,
        const float* __restrict__ w1, const float* __restrict__ b1,
        const float* __restrict__ u1,
        const float* __restrict__ w2, const float* __restrict__ b2,
        const float* __restrict__ u2,
        const float* __restrict__ w3) {
    int t = threadIdx.x;
    __shared__ float smem[1152];   // aliased: sv uses 1024, mlp uses 1152

    if (blockIdx.x == 0) {
        // ---------------- spectral norms ----------------
        float* buf = smem;          // [512]
        float* red = smem + Cn;     // [512]
        int o8 = t >> 3, k8 = t & 7;

        // ----- sv1 : Wm1 [64, 512] -----
        float v = 0.f;
#pragma unroll 8
        for (int i = 0; i < CR; i++) v += u1[i] * w1[i * Cn + t];
        red[t] = v * v;
        __syncthreads();
        for (int o = 256; o; o >>= 1) { if (t < o) red[t] += red[t + o]; __syncthreads(); }
        float nv = sqrtf(red[0]);
        __syncthreads();
        buf[t] = v / fmaxf(nv, EPS);
        __syncthreads();
        {
            float tv = 0.f;
#pragma unroll 8
            for (int j = k8 * 64; j < k8 * 64 + 64; j++) tv += w1[o8 * Cn + j] * buf[j];
#pragma unroll
            for (int o = 4; o; o >>= 1) tv += __shfl_down_sync(0xffffffffu, tv, o, 8);
            __syncthreads();
            if (k8 == 0) red[o8] = tv * tv;
            __syncthreads();
            if (t < 32) {
                float r = red[t] + red[t + 32];
#pragma unroll
                for (int o = 16; o; o >>= 1) r += __shfl_down_sync(0xffffffffu, r, o);
                if (t == 0) { float nt = sqrtf(r); g_sv[0] = nt * nt / fmaxf(nt, EPS); }
            }
            __syncthreads();
        }

        // ----- sv2 : Wm2 [512, 64] -----
        {
            float v2 = 0.f;
#pragma unroll 8
            for (int i = k8 * 64; i < k8 * 64 + 64; i++) v2 += u2[i] * w2[i * CR + o8];
#pragma unroll
            for (int o = 4; o; o >>= 1) v2 += __shfl_down_sync(0xffffffffu, v2, o, 8);
            __syncthreads();
            if (k8 == 0) red[o8] = v2 * v2;
            __syncthreads();
            if (t < 32) {
                float r = red[t] + red[t + 32];
#pragma unroll
                for (int o = 16; o; o >>= 1) r += __shfl_down_sync(0xffffffffu, r, o);
                if (t == 0) red[0] = sqrtf(r);
            }
            __syncthreads();
            float n2 = red[0];
            __syncthreads();
            if (k8 == 0) buf[o8] = v2 / fmaxf(n2, EPS);
            __syncthreads();
            float t2 = 0.f;
#pragma unroll 8
            for (int j = 0; j < CR; j++) t2 += w2[t * CR + j] * buf[j];
            red[t] = t2 * t2;
            __syncthreads();
            for (int o = 256; o; o >>= 1) { if (t < o) red[t] += red[t + o]; __syncthreads(); }
            if (t == 0) { float nt = sqrtf(red[0]); g_sv[1] = nt * nt / fmaxf(nt, EPS); }
        }

        // ----- sv3 = ||w3||_F -----
        if (t == 0) {
            float nn = 0.f;
            for (int k = 0; k < 18; k++) nn += w3[k] * w3[k];
            g_sv[2] = sqrtf(nn);
        }
        __syncthreads();
        if (t == 0) {
            __threadfence();
            for (int b = 0; b < Bn; b++) atomicAdd(&c_stats[b], 1u);
        }
        return;
    }

    if (blockIdx.x <= 1024) {
        // ---------------- per-(b,c) stats: one warp per row ----------------
        int warp = t >> 5, lane = t & 31;
        int bc = (blockIdx.x - 1) * 16 + warp;
        int batch = (blockIdx.x - 1) >> 5;      // 32 blocks per batch
        const float4* row = reinterpret_cast<const float4*>(x + (size_t)bc * HW);
        float s = 0.f, m = -FLT_MAX;
#pragma unroll 8
        for (int k = 0; k < 32; k++) {
            float4 v = __ldcs(row + lane + k * 32);
            s += (v.x + v.y) + (v.z + v.w);
            m = fmaxf(m, fmaxf(fmaxf(v.x, v.y), fmaxf(v.z, v.w)));
        }
#pragma unroll
        for (int o = 16; o; o >>= 1) {
            s += __shfl_down_sync(0xffffffffu, s, o);
            m = fmaxf(m, __shfl_down_sync(0xffffffffu, m, o));
        }
        if (lane == 0) {
            g_avg[bc] = s * (1.f / HW);
            g_mx [bc] = m;
        }
        __syncthreads();
        if (t == 0) {
            __threadfence();
            atomicAdd(&c_stats[batch], 1u);
        }
        return;
    }

    // ---------------- MLP for batch b (waits for 33 arrivals/epoch) ----------------
    {
        int b = blockIdx.x - 1025;
        if (t == 0) {
            unsigned e = atomicAdd(&t_mlp[b], 1u);
            unsigned target = (e + 1u) * 33u;
            volatile unsigned* p = &c_stats[b];
            while ((int)(*p - target) < 0) __nanosleep(64);
            __threadfence();
        }
        __syncthreads();

        float* sa = smem;               // [512]
        float* sx = smem + Cn;          // [512]
        float* ha = smem + 2 * Cn;      // [64]
        float* hm = smem + 2 * Cn + CR; // [64]
        int o8 = t >> 3, k8 = t & 7;
        sa[t] = g_avg[b * Cn + t];
        sx[t] = g_mx [b * Cn + t];
        __syncthreads();
        float inv1 = 1.f / g_sv[0];
        float inv2 = 1.f / g_sv[1];
        {
            float xa = 0.f, xm = 0.f;
#pragma unroll 8
            for (int c = k8 * 64; c < k8 * 64 + 64; c++) {
                float w = w1[o8 * Cn + c];
                xa += w * sa[c];
                xm += w * sx[c];
            }
#pragma unroll
            for (int o = 4; o; o >>= 1) {
                xa += __shfl_down_sync(0xffffffffu, xa, o, 8);
                xm += __shfl_down_sync(0xffffffffu, xm, o, 8);
            }
            if (k8 == 0) {
                float bb = b1[o8];
                ha[o8] = fmaxf(xa * inv1 + bb, 0.f);
                hm[o8] = fmaxf(xm * inv1 + bb, 0.f);
            }
        }
        __syncthreads();
        float a = 0.f, m = 0.f;
#pragma unroll 8
        for (int k = 0; k < CR; k++) {
            float w = w2[t * CR + k];
            a += w * ha[k];
            m += w * hm[k];
        }
        float bb = b2[t];
        a = a * inv2 + bb;
        m = m * inv2 + bb;
        g_s[b * Cn + t] = 1.f / (1.f + expf(-(a + m)));
    }
}

// ============================================================
// K2: grid = (40, 32), 512 threads.
//  x in [0,32)  : pool — per-pixel mean/max of x*s -> ca, cm
//  x in [32,40) : conv slot — waits on c_pool[b], 512 px each,
//                 3x3 conv + sigmoid -> g_sig
// ============================================================
__global__ void __launch_bounds__(512)
k_pool(const float* __restrict__ x, const float* __restrict__ w3,
       const float* __restrict__ b3) {
    int b = blockIdx.y;
    int tid = threadIdx.x;

    if (blockIdx.x < 32) {
        int p0 = blockIdx.x * 128;           // 128 pixels per block
        int g  = tid & 31;                   // float4 pixel-group 0..31
        int ch = tid >> 5;                   // channel-chunk 0..15
        __shared__ float ss[Cn];
        __shared__ float4 rs[16][32];
        __shared__ float4 rm[16][32];
        ss[tid] = g_s[b * Cn + tid];
        __syncthreads();

        const float* xb = x + (size_t)b * Cn * HW + p0 + g * 4;
        float4 sum = make_float4(0.f, 0.f, 0.f, 0.f);
        float4 mx  = make_float4(-FLT_MAX, -FLT_MAX, -FLT_MAX, -FLT_MAX);
#pragma unroll 8
        for (int cc = 0; cc < 32; cc++) {
            int c = ch * 32 + cc;
            float4 v = *reinterpret_cast<const float4*>(xb + (size_t)c * HW);
            float s = ss[c];
            v.x *= s; v.y *= s; v.z *= s; v.w *= s;
            sum.x += v.x; sum.y += v.y; sum.z += v.z; sum.w += v.w;
            mx.x = fmaxf(mx.x, v.x); mx.y = fmaxf(mx.y, v.y);
            mx.z = fmaxf(mx.z, v.z); mx.w = fmaxf(mx.w, v.w);
        }
        rs[ch][g] = sum; rm[ch][g] = mx;
        __syncthreads();
#pragma unroll
        for (int o = 8; o; o >>= 1) {
            if (ch < o) {
                float4 a = rs[ch][g], c2 = rs[ch + o][g];
                a.x += c2.x; a.y += c2.y; a.z += c2.z; a.w += c2.w;
                rs[ch][g] = a;
                float4 m1 = rm[ch][g], m2 = rm[ch + o][g];
                m1.x = fmaxf(m1.x, m2.x); m1.y = fmaxf(m1.y, m2.y);
                m1.z = fmaxf(m1.z, m2.z); m1.w = fmaxf(m1.w, m2.w);
                rm[ch][g] = m1;
            }
            __syncthreads();
        }
        if (ch == 0) {
            float4 a = rs[0][g];
            a.x *= (1.f / Cn); a.y *= (1.f / Cn); a.z *= (1.f / Cn); a.w *= (1.f / Cn);
            *reinterpret_cast<float4*>(g_ca + b * HW + p0 + g * 4) = a;
            *reinterpret_cast<float4*>(g_cm + b * HW + p0 + g * 4) = rm[0][g];
        }
        __syncthreads();
        if (tid == 0) {
            __threadfence();
            atomicAdd(&c_pool[b], 1u);
        }
        return;
    }

    // ---------------- conv slot: waits for this batch's 32 pool blocks ----------------
    {
        int slot = blockIdx.x - 32;          // 0..7
        __shared__ float wc[20];
        if (tid < 18) wc[tid] = w3[tid];
        if (tid == 18) wc[18] = b3[0];
        if (tid == 19) wc[19] = 1.f / g_sv[2];
        if (tid == 0) {
            unsigned e = atomicAdd(&t_conv[b * 8 + slot], 1u);
            unsigned target = (e + 1u) * 32u;
            volatile unsigned* p = &c_pool[b];
            while ((int)(*p - target) < 0) __nanosleep(64);
            __threadfence();
        }
        __syncthreads();

        int p = slot * 512 + tid;
        int h = p >> 6, w = p & 63;
        const float* ca = g_ca + b * HW;
        const float* cm = g_cm + b * HW;
        float y = 0.f;
#pragma unroll
        for (int dy = -1; dy <= 1; dy++) {
            int hh = h + dy;
            if (hh < 0 || hh >= Hd) continue;
#pragma unroll
            for (int dx = -1; dx <= 1; dx++) {
                int ww = w + dx;
                if (ww < 0 || ww >= Wd) continue;
                int q = hh * Wd + ww;
                int ki = (dy + 1) * 3 + (dx + 1);
                y += wc[ki] * ca[q] + wc[9 + ki] * cm[q];
            }
        }
        y = y * wc[19] + wc[18];
        g_sig[b * HW + p] = 1.f / (1.f + expf(-y));
    }
}

// ============================================================
// K3: pointwise out = x * s[b,c] * sig[b,p], 2 channels/block
// (R11-measured best: 76.2us @ 80.4% DRAM). grid = 8192, block = 256.
// ============================================================
__global__ void k_out(const float* __restrict__ x, float* __restrict__ out) {
    int blk = blockIdx.x;                // 0..8191
    int b = blk >> 8;                    // /256
    int c0 = (blk & 255) * 2;
    float s0 = g_s[b * Cn + c0];
    float s1 = g_s[b * Cn + c0 + 1];
    const float4* x0 = reinterpret_cast<const float4*>(x + ((size_t)b * Cn + c0) * HW);
    const float4* x1 = x0 + HW / 4;
    float4* o0 = reinterpret_cast<float4*>(out + ((size_t)b * Cn + c0) * HW);
    float4* o1 = o0 + HW / 4;
    const float4* sg = reinterpret_cast<const float4*>(g_sig + b * HW);
    int tid = threadIdx.x;
#pragma unroll
    for (int k = 0; k < 4; k++) {
        int i = k * 256 + tid;
        float4 gv = sg[i];
        float4 v0 = __ldcs(x0 + i);
        float4 v1 = __ldcs(x1 + i);
        v0.x *= s0 * gv.x; v0.y *= s0 * gv.y; v0.z *= s0 * gv.z; v0.w *= s0 * gv.w;
        v1.x *= s1 * gv.x; v1.y *= s1 * gv.y; v1.z *= s1 * gv.z; v1.w *= s1 * gv.w;
        __stcs(o0 + i, v0);
        __stcs(o1 + i, v1);
    }
}

// ============================================================
extern "C" void kernel_launch(void* const* d_in, const int* in_sizes, int n_in,
                              void* d_out, int out_size) {
    const float* x  = (const float*)d_in[0];
    const float* w1 = (const float*)d_in[1];
    const float* b1 = (const float*)d_in[2];
    const float* u1 = (const float*)d_in[3];
    const float* w2 = (const float*)d_in[4];
    const float* b2 = (const float*)d_in[5];
    const float* u2 = (const float*)d_in[6];
    const float* w3 = (const float*)d_in[7];
    const float* b3 = (const float*)d_in[8];
    // d_in[9] = u3: unused (sv3 reduces to ||w3||_F)
    float* out = (float*)d_out;

    k_stats<<<1 + 1024 + Bn, 512>>>(x, w1, b1, u1, w2, b2, u2, w3);
    k_pool<<<dim3(40, Bn), 512>>>(x, w3, b3);
    k_out<<<Bn * Cn / 2, 256>>>(x, out);
}

// round 14
// speedup vs baseline: 1.3315x; 1.3315x over previous
#include <cuda_runtime.h>
#include <math.h>
#include <float.h>

#define Bn 32
#define Cn 512
#define CR 64
#define Hd 64
#define Wd 64
#define HW 4096
#define EPS 1e-12f

// ---- scratch (no allocation allowed) ----
__device__ float    g_sum_acc[Bn * Cn];   // zeroed by k_mlp each launch
__device__ unsigned g_max_acc[Bn * Cn];   // order-encoded float; zeroed by k_mlp
__device__ float g_s  [Bn * Cn];
__device__ float g_sv [4];
__device__ float g_ca [Bn * HW];
__device__ float g_cm [Bn * HW];
__device__ float g_sig[Bn * HW];

// order-preserving float<->uint map (0 sorts below every encoded float)
__device__ __forceinline__ unsigned fenc(float f) {
    unsigned u = __float_as_uint(f);
    return (u & 0x80000000u) ? ~u : (u | 0x80000000u);
}
__device__ __forceinline__ float fdec(unsigned u) {
    return (u & 0x80000000u) ? __uint_as_float(u ^ 0x80000000u)
                             : __uint_as_float(~u);
}

// ============================================================
// K1: block 0 = spectral norms; blocks 1..1024 = stats with the
// k_pool-proven access pattern + atomic cross-block reduction.
// grid = 1025, block = 512 (16 chan-chunk warps x 32 pixel-group lanes).
// ============================================================
__global__ void __launch_bounds__(512)
k_stats(const float* __restrict__ x,
        const float* __restrict__ w1, const float* __restrict__ u1,
        const float* __restrict__ w2, const float* __restrict__ u2,
        const float* __restrict__ w3) {
    int t = threadIdx.x;

    if (blockIdx.x == 0) {
        // ---------------- spectral norms, 512 threads ----------------
        __shared__ float buf[Cn];
        __shared__ float red[Cn];
        int o8 = t >> 3, k8 = t & 7;

        // ----- sv1 : Wm1 [64, 512] -----
        float v = 0.f;
#pragma unroll 8
        for (int i = 0; i < CR; i++) v += u1[i] * w1[i * Cn + t];
        red[t] = v * v;
        __syncthreads();
        for (int o = 256; o; o >>= 1) { if (t < o) red[t] += red[t + o]; __syncthreads(); }
        float nv = sqrtf(red[0]);
        __syncthreads();
        buf[t] = v / fmaxf(nv, EPS);
        __syncthreads();
        {
            float tv = 0.f;
#pragma unroll 8
            for (int j = k8 * 64; j < k8 * 64 + 64; j++) tv += w1[o8 * Cn + j] * buf[j];
#pragma unroll
            for (int o = 4; o; o >>= 1) tv += __shfl_down_sync(0xffffffffu, tv, o, 8);
            __syncthreads();
            if (k8 == 0) red[o8] = tv * tv;
            __syncthreads();
            if (t < 32) {
                float r = red[t] + red[t + 32];
#pragma unroll
                for (int o = 16; o; o >>= 1) r += __shfl_down_sync(0xffffffffu, r, o);
                if (t == 0) { float nt = sqrtf(r); g_sv[0] = nt * nt / fmaxf(nt, EPS); }
            }
            __syncthreads();
        }

        // ----- sv2 : Wm2 [512, 64] -----
        {
            float v2 = 0.f;
#pragma unroll 8
            for (int i = k8 * 64; i < k8 * 64 + 64; i++) v2 += u2[i] * w2[i * CR + o8];
#pragma unroll
            for (int o = 4; o; o >>= 1) v2 += __shfl_down_sync(0xffffffffu, v2, o, 8);
            __syncthreads();
            if (k8 == 0) red[o8] = v2 * v2;
            __syncthreads();
            if (t < 32) {
                float r = red[t] + red[t + 32];
#pragma unroll
                for (int o = 16; o; o >>= 1) r += __shfl_down_sync(0xffffffffu, r, o);
                if (t == 0) red[0] = sqrtf(r);
            }
            __syncthreads();
            float n2 = red[0];
            __syncthreads();
            if (k8 == 0) buf[o8] = v2 / fmaxf(n2, EPS);
            __syncthreads();
            float t2 = 0.f;
#pragma unroll 8
            for (int j = 0; j < CR; j++) t2 += w2[t * CR + j] * buf[j];
            red[t] = t2 * t2;
            __syncthreads();
            for (int o = 256; o; o >>= 1) { if (t < o) red[t] += red[t + o]; __syncthreads(); }
            if (t == 0) { float nt = sqrtf(red[0]); g_sv[1] = nt * nt / fmaxf(nt, EPS); }
        }

        // ----- sv3 = ||w3||_F -----
        if (t == 0) {
            float nn = 0.f;
            for (int k = 0; k < 18; k++) nn += w3[k] * w3[k];
            g_sv[2] = sqrtf(nn);
        }
        return;
    }

    // ---------------- stats: pool-shaped reads + atomic reduce ----------------
    int idx = blockIdx.x - 1;            // 0..1023
    int b   = idx >> 5;                  // 32 tiles per batch
    int p0  = (idx & 31) * 128;          // 128-pixel tile
    int g   = t & 31;                    // pixel-group (lane)
    int ch  = t >> 5;                    // channel-chunk (warp)
    const float* xb = x + (size_t)b * Cn * HW + p0 + g * 4;
    unsigned* mx_acc = g_max_acc + b * Cn;
    float*    sm_acc = g_sum_acc + b * Cn;
#pragma unroll 8
    for (int cc = 0; cc < 32; cc++) {
        int c = ch * 32 + cc;
        float4 v = __ldcs(reinterpret_cast<const float4*>(xb + (size_t)c * HW));
        float s = (v.x + v.y) + (v.z + v.w);
        float m = fmaxf(fmaxf(v.x, v.y), fmaxf(v.z, v.w));
#pragma unroll
        for (int o = 16; o; o >>= 1) {
            s += __shfl_down_sync(0xffffffffu, s, o);
            m = fmaxf(m, __shfl_down_sync(0xffffffffu, m, o));
        }
        if (g == 0) {
            atomicAdd(sm_acc + c, s);
            atomicMax(mx_acc + c, fenc(m));
        }
    }
}

// ============================================================
// K2: channel-attention MLP + sigmoid -> s[B,C].
// Reads accumulators, ZEROES them for the next graph replay.
// grid = 32, block = 512. Hidden layer: 8 threads per output.
// ============================================================
__global__ void k_mlp(const float* __restrict__ w1, const float* __restrict__ b1,
                      const float* __restrict__ w2, const float* __restrict__ b2) {
    int b = blockIdx.x, t = threadIdx.x;
    int o8 = t >> 3, k8 = t & 7;
    __shared__ float sa[Cn], sx[Cn], ha[CR], hm[CR];
    sa[t] = g_sum_acc[b * Cn + t] * (1.f / HW);
    sx[t] = fdec(g_max_acc[b * Cn + t]);
    g_sum_acc[b * Cn + t] = 0.f;         // reset for next launch
    g_max_acc[b * Cn + t] = 0u;
    __syncthreads();
    float inv1 = 1.f / g_sv[0];
    float inv2 = 1.f / g_sv[1];
    {
        float xa = 0.f, xm = 0.f;
#pragma unroll 8
        for (int c = k8 * 64; c < k8 * 64 + 64; c++) {
            float w = w1[o8 * Cn + c];
            xa += w * sa[c];
            xm += w * sx[c];
        }
#pragma unroll
        for (int o = 4; o; o >>= 1) {
            xa += __shfl_down_sync(0xffffffffu, xa, o, 8);
            xm += __shfl_down_sync(0xffffffffu, xm, o, 8);
        }
        if (k8 == 0) {
            float bb = b1[o8];
            ha[o8] = fmaxf(xa * inv1 + bb, 0.f);
            hm[o8] = fmaxf(xm * inv1 + bb, 0.f);
        }
    }
    __syncthreads();
    float a = 0.f, m = 0.f;
#pragma unroll 8
    for (int k = 0; k < CR; k++) {
        float w = w2[t * CR + k];
        a += w * ha[k];
        m += w * hm[k];
    }
    float bb = b2[t];
    a = a * inv2 + bb;
    m = m * inv2 + bb;
    g_s[b * Cn + t] = 1.f / (1.f + expf(-(a + m)));
}

// ============================================================
// K3: per-pixel mean/max over channels of x*s -> ca, cm.
// grid = (32, 32), block = 512 = 16 chan-chunks x 32 float4-groups.
// (R7/R11-measured shape: 77% DRAM, 45us)
// ============================================================
__global__ void k_pool(const float* __restrict__ x) {
    int b = blockIdx.y;
    int p0 = blockIdx.x * 128;           // 128 pixels per block
    int tid = threadIdx.x;
    int g  = tid & 31;                   // float4 pixel-group 0..31
    int ch = tid >> 5;                   // channel-chunk 0..15
    __shared__ float ss[Cn];
    __shared__ float4 rs[16][32];
    __shared__ float4 rm[16][32];
    ss[tid] = g_s[b * Cn + tid];
    __syncthreads();

    const float* xb = x + (size_t)b * Cn * HW + p0 + g * 4;
    float4 sum = make_float4(0.f, 0.f, 0.f, 0.f);
    float4 mx  = make_float4(-FLT_MAX, -FLT_MAX, -FLT_MAX, -FLT_MAX);
#pragma unroll 8
    for (int cc = 0; cc < 32; cc++) {
        int c = ch * 32 + cc;
        float4 v = *reinterpret_cast<const float4*>(xb + (size_t)c * HW);
        float s = ss[c];
        v.x *= s; v.y *= s; v.z *= s; v.w *= s;
        sum.x += v.x; sum.y += v.y; sum.z += v.z; sum.w += v.w;
        mx.x = fmaxf(mx.x, v.x); mx.y = fmaxf(mx.y, v.y);
        mx.z = fmaxf(mx.z, v.z); mx.w = fmaxf(mx.w, v.w);
    }
    rs[ch][g] = sum; rm[ch][g] = mx;
    __syncthreads();
#pragma unroll
    for (int o = 8; o; o >>= 1) {
        if (ch < o) {
            float4 a = rs[ch][g], c2 = rs[ch + o][g];
            a.x += c2.x; a.y += c2.y; a.z += c2.z; a.w += c2.w;
            rs[ch][g] = a;
            float4 m1 = rm[ch][g], m2 = rm[ch + o][g];
            m1.x = fmaxf(m1.x, m2.x); m1.y = fmaxf(m1.y, m2.y);
            m1.z = fmaxf(m1.z, m2.z); m1.w = fmaxf(m1.w, m2.w);
            rm[ch][g] = m1;
        }
        __syncthreads();
    }
    if (ch == 0) {
        float4 a = rs[0][g];
        a.x *= (1.f / Cn); a.y *= (1.f / Cn); a.z *= (1.f / Cn); a.w *= (1.f / Cn);
        *reinterpret_cast<float4*>(g_ca + b * HW + p0 + g * 4) = a;
        *reinterpret_cast<float4*>(g_cm + b * HW + p0 + g * 4) = rm[0][g];
    }
}

// ============================================================
// K4: 3x3 conv on (ca, cm) -> g_sig = sigmoid(y).
// ca/cm are L2-resident (1 MB). grid = (16, 32), block = 256.
// ============================================================
__global__ void k_conv(const float* __restrict__ w3, const float* __restrict__ b3) {
    int b = blockIdx.y;
    int p = blockIdx.x * 256 + threadIdx.x;
    int h = p >> 6, w = p & 63;
    __shared__ float wc[20];
    if (threadIdx.x < 18) wc[threadIdx.x] = w3[threadIdx.x];
    if (threadIdx.x == 18) wc[18] = b3[0];
    if (threadIdx.x == 19) wc[19] = 1.f / g_sv[2];
    __syncthreads();

    const float* ca = g_ca + b * HW;
    const float* cm = g_cm + b * HW;
    float y = 0.f;
#pragma unroll
    for (int dy = -1; dy <= 1; dy++) {
        int hh = h + dy;
        if (hh < 0 || hh >= Hd) continue;
#pragma unroll
        for (int dx = -1; dx <= 1; dx++) {
            int ww = w + dx;
            if (ww < 0 || ww >= Wd) continue;
            int q = hh * Wd + ww;
            int ki = (dy + 1) * 3 + (dx + 1);
            y += wc[ki] * ca[q] + wc[9 + ki] * cm[q];
        }
    }
    y = y * wc[19] + wc[18];
    g_sig[b * HW + p] = 1.f / (1.f + expf(-y));
}

// ============================================================
// K5: pointwise out = x * s[b,c] * sig[b,p], 2 channels/block.
// (R11-measured best: 76.2us @ 80.4% DRAM). grid = 8192, block = 256.
// ============================================================
__global__ void k_out(const float* __restrict__ x, float* __restrict__ out) {
    int blk = blockIdx.x;                // 0..8191
    int b = blk >> 8;                    // /256
    int c0 = (blk & 255) * 2;
    float s0 = g_s[b * Cn + c0];
    float s1 = g_s[b * Cn + c0 + 1];
    const float4* x0 = reinterpret_cast<const float4*>(x + ((size_t)b * Cn + c0) * HW);
    const float4* x1 = x0 + HW / 4;
    float4* o0 = reinterpret_cast<float4*>(out + ((size_t)b * Cn + c0) * HW);
    float4* o1 = o0 + HW / 4;
    const float4* sg = reinterpret_cast<const float4*>(g_sig + b * HW);
    int tid = threadIdx.x;
#pragma unroll
    for (int k = 0; k < 4; k++) {
        int i = k * 256 + tid;
        float4 gv = sg[i];
        float4 v0 = __ldcs(x0 + i);
        float4 v1 = __ldcs(x1 + i);
        v0.x *= s0 * gv.x; v0.y *= s0 * gv.y; v0.z *= s0 * gv.z; v0.w *= s0 * gv.w;
        v1.x *= s1 * gv.x; v1.y *= s1 * gv.y; v1.z *= s1 * gv.z; v1.w *= s1 * gv.w;
        __stcs(o0 + i, v0);
        __stcs(o1 + i, v1);
    }
}

// ============================================================
extern "C" void kernel_launch(void* const* d_in, const int* in_sizes, int n_in,
                              void* d_out, int out_size) {
    const float* x  = (const float*)d_in[0];
    const float* w1 = (const float*)d_in[1];
    const float* b1 = (const float*)d_in[2];
    const float* u1 = (const float*)d_in[3];
    const float* w2 = (const float*)d_in[4];
    const float* b2 = (const float*)d_in[5];
    const float* u2 = (const float*)d_in[6];
    const float* w3 = (const float*)d_in[7];
    const float* b3 = (const float*)d_in[8];
    // d_in[9] = u3: unused (sv3 reduces to ||w3||_F)
    float* out = (float*)d_out;

    k_stats<<<1 + 1024, 512>>>(x, w1, u1, w2, u2, w3);
    k_mlp<<<Bn, Cn>>>(w1, b1, w2, b2);
    k_pool<<<dim3(HW / 128, Bn), 512>>>(x);
    k_conv<<<dim3(HW / 256, Bn), 256>>>(w3, b3);
    k_out<<<Bn * Cn / 2, 256>>>(x, out);
}